// round 14
// baseline (speedup 1.0000x reference)
#include <cuda_runtime.h>
#include <cstdint>

#define B 8
#define C 256
#define N 3136
#define NP 3200
#define NQ (N/4)
#define NC 50
#define TILE 128
#define KT 16
#define NT 25
#define NPAIRS (NT*(NT+1)/2)
#define ASEGS 200              // NP/16
#define BSEGS 400              // NP/8
#define DSMEM_BYTES 47104      // 11776 floats

// ---------------- scratch (static device globals: allocation-guard safe) ----
__device__ float g_d2[(size_t)B * N * N];
__device__ __align__(16) float g_ah[(size_t)B * ASEGS * 32 * 128];
__device__ __align__(16) float g_al[(size_t)B * ASEGS * 32 * 128];
__device__ __align__(16) float g_bh[(size_t)B * BSEGS * 32 * 64];
__device__ __align__(16) float g_bl[(size_t)B * BSEGS * 32 * 64];
__device__ float    g_sq[B * N];
__device__ float    g_dens[B * N];
__device__ float    g_score[B * N];
__device__ unsigned g_maxb[B];
__device__ int      g_idx[B * NC];

// ---------------- threefry-2x32 (JAX-compatible) ---------------------------
__device__ __forceinline__ uint32_t rotl32(uint32_t x, int r) {
    return (x << r) | (x >> (32 - r));
}

__device__ __forceinline__ void threefry2x32_k42(uint32_t x0, uint32_t x1,
                                                 uint32_t& o0, uint32_t& o1) {
    const uint32_t ks0 = 0u;
    const uint32_t ks1 = 42u;
    const uint32_t ks2 = 0x1BD11BDAu ^ 42u;
    x0 += ks0; x1 += ks1;
#define TF_RND(r) { x0 += x1; x1 = rotl32(x1, r); x1 ^= x0; }
    TF_RND(13) TF_RND(15) TF_RND(26) TF_RND(6)
    x0 += ks1; x1 += ks2 + 1u;
    TF_RND(17) TF_RND(29) TF_RND(16) TF_RND(24)
    x0 += ks2; x1 += ks0 + 2u;
    TF_RND(13) TF_RND(15) TF_RND(26) TF_RND(6)
    x0 += ks0; x1 += ks1 + 3u;
    TF_RND(17) TF_RND(29) TF_RND(16) TF_RND(24)
    x0 += ks1; x1 += ks2 + 4u;
    TF_RND(13) TF_RND(15) TF_RND(26) TF_RND(6)
    x0 += ks2; x1 += ks0 + 5u;
#undef TF_RND
    o0 = x0; o1 = x1;
}

__device__ __forceinline__ float jax_uniform_noise(int g) {
    const int half = (B * N) / 2;  // 12544
    uint32_t lane = (g < half) ? (uint32_t)g : (uint32_t)(g - half);
    uint32_t o0, o1;
    threefry2x32_k42(lane, lane + (uint32_t)half, o0, o1);
    uint32_t bits = (g < half) ? o0 : o1;
    return __uint_as_float((bits >> 9) | 0x3F800000u) - 1.0f;
}

// ---------------- tf32 + f32x2 helpers ---------------------------------------
__device__ __forceinline__ uint32_t tf32r(float x) {
    uint32_t y;
    asm("cvt.rna.tf32.f32 %0, %1;" : "=r"(y) : "f"(x));
    return y;
}

__device__ __forceinline__ void split1(float v, float& h, float& l) {
    float hf = __uint_as_float(tf32r(v));
    h = hf;
    l = __uint_as_float(tf32r(v - hf));
}

__device__ __forceinline__ void mma8(float d[4], const uint32_t a[4], const uint32_t b[2]) {
    asm volatile(
        "mma.sync.aligned.m16n8k8.row.col.f32.tf32.tf32.f32 "
        "{%0,%1,%2,%3}, {%4,%5,%6,%7}, {%8,%9}, {%0,%1,%2,%3};"
        : "+f"(d[0]), "+f"(d[1]), "+f"(d[2]), "+f"(d[3])
        : "r"(a[0]), "r"(a[1]), "r"(a[2]), "r"(a[3]), "r"(b[0]), "r"(b[1]));
}

__device__ __forceinline__ unsigned long long ffma2(unsigned long long a,
                                                    unsigned long long b,
                                                    unsigned long long c) {
    unsigned long long d;
    asm("fma.rn.f32x2 %0, %1, %2, %3;" : "=l"(d) : "l"(a), "l"(b), "l"(c));
    return d;
}

__device__ __forceinline__ unsigned long long dup2(float a) {
    unsigned long long d;
    asm("mov.b64 %0, {%1, %1};" : "=l"(d) : "f"(a));
    return d;
}

__device__ __forceinline__ void barg(int id, int cnt) {
    asm volatile("bar.sync %0, %1;" :: "r"(id), "r"(cnt) : "memory");
}

// ---------------- kernels ---------------------------------------------------
__global__ void init_kernel() {
    int t = threadIdx.x;
    if (t < B) g_maxb[t] = 0u;
}

__global__ void sq_kernel(const float* __restrict__ x) {
    int g = blockIdx.x * blockDim.x + threadIdx.x;
    if (g >= B * N) return;
    int b = g / N, n = g % N;
    const float* p = x + (size_t)b * C * N + n;
    float s = 0.f;
#pragma unroll 8
    for (int c = 0; c < C; c++) {
        float v = p[(size_t)c * N];
        s = fmaf(v, v, s);
    }
    g_sq[g] = s;
}

// transpose + tf32 hi/lo split into global fragment layouts (tensor operands)
__global__ void split_kernel(const float* __restrict__ x) {
    const int seg = blockIdx.x;
    const int b = blockIdx.y;
    const int row0 = seg * 16;
    __shared__ float sv[16][260];
    const int t = threadIdx.x;
#pragma unroll
    for (int i = 0; i < 16; i++) {
        int r = t & 15;
        int k = (t >> 4) + i * 16;
        int row = row0 + r;
        float v = (row < N) ? x[((size_t)b * C + k) * N + row] : 0.f;
        sv[r][k] = v;
    }
    __syncthreads();
#pragma unroll
    for (int j = 0; j < 4; j++) {
        int u = t + j * 256;
        int k8 = u >> 5, lane = u & 31;
        int rl = lane >> 2, tg = lane & 3;
        int k = k8 * 8 + tg;
        float4 hv, lv;
        split1(sv[rl][k],         hv.x, lv.x);
        split1(sv[rl + 8][k],     hv.y, lv.y);
        split1(sv[rl][k + 4],     hv.z, lv.z);
        split1(sv[rl + 8][k + 4], hv.w, lv.w);
        size_t base = (((size_t)b * ASEGS + seg) * 32 + k8) * 128 + lane * 4;
        *reinterpret_cast<float4*>(&g_ah[base]) = hv;
        *reinterpret_cast<float4*>(&g_al[base]) = lv;
    }
#pragma unroll
    for (int j = 0; j < 8; j++) {
        int u = t + j * 256;
        int cs = u >> 10, rem = u & 1023;
        int k8 = rem >> 5, lane = rem & 31;
        int col = cs * 8 + (lane >> 2), tg = lane & 3;
        int k = k8 * 8 + tg;
        float2 hv, lv;
        split1(sv[col][k],     hv.x, lv.x);
        split1(sv[col][k + 4], hv.y, lv.y);
        size_t base = (((size_t)b * BSEGS + seg * 2 + cs) * 32 + k8) * 64 + lane * 2;
        *reinterpret_cast<float2*>(&g_bh[base]) = hv;
        *reinterpret_cast<float2*>(&g_bl[base]) = lv;
    }
}

// INTRA-CTA HYBRID Gram (R11 config), PER-BATCH launch: warps 0-5 = fp32
// f32x2 (cols 0..95), warps 6-7 = tf32x3 mma.sync (cols 96..127).
__global__ __launch_bounds__(256, 2) void gram_kernel(const float* __restrict__ x, int b) {
    extern __shared__ float dynf[];
    __shared__ float red[256];

    int rem = blockIdx.x;
    int ti = 0;
    while (rem >= NT - ti) { rem -= NT - ti; ti++; }
    const int tj = ti + rem;
    const int i0 = ti * TILE, j0 = tj * TILE;

    const int tid = threadIdx.x, lane = tid & 31;
    const float* SQ = &g_sq[b * N];
    const size_t bN = (size_t)b * N;
    float tmax = 0.f;
    const float4 f40 = make_float4(0.f, 0.f, 0.f, 0.f);

    if (tid < 192) {
        // ===================== FP32 GROUP (6 warps, cols 0..95) ==============
        const float* X = x + (size_t)b * C * N;
        const int tx = tid % 12, ty = tid / 12;

        float4 pa0, pa1, pa2, pb0, pb1;
#define LDA(s, dst, k0) { int kk_=(s)>>5, f4_=(s)&31; int ic_=i0+f4_*4;       \
        dst = (ic_<N)? *reinterpret_cast<const float4*>(&X[(size_t)((k0)+kk_)*N+ic_]) : f40; }
#define LDB(s, dst, k0) { int kk_=(s)/24, c_=(s)%24; int jc_=j0+c_*4;         \
        dst = (jc_<N)? *reinterpret_cast<const float4*>(&X[(size_t)((k0)+kk_)*N+jc_]) : f40; }
#define LOADK(k0) { LDA(tid, pa0, k0); LDA(tid+192, pa1, k0);                  \
        if (tid < 128) LDA(tid+384, pa2, k0);                                  \
        LDB(tid, pb0, k0); LDB(tid+192, pb1, k0); }

        unsigned long long acc2[8][4];
#pragma unroll
        for (int r = 0; r < 8; r++)
#pragma unroll
            for (int c = 0; c < 4; c++) acc2[r][c] = 0ull;

        LOADK(0);
#pragma unroll 2
        for (int kt = 0; kt < C / KT; kt++) {
            const int boA = (kt & 1) * 2048;
            const int boB = 4096 + (kt & 1) * 1536;
            { int s=tid;     *reinterpret_cast<float4*>(&dynf[boA+(s>>5)*128+(s&31)*4]) = pa0; }
            { int s=tid+192; *reinterpret_cast<float4*>(&dynf[boA+(s>>5)*128+(s&31)*4]) = pa1; }
            if (tid < 128) { int s=tid+384; *reinterpret_cast<float4*>(&dynf[boA+(s>>5)*128+(s&31)*4]) = pa2; }
            { int s=tid;     *reinterpret_cast<float4*>(&dynf[boB+(s/24)*96+(s%24)*4]) = pb0; }
            { int s=tid+192; *reinterpret_cast<float4*>(&dynf[boB+(s/24)*96+(s%24)*4]) = pb1; }
            barg(1, 192);
            if (kt + 1 < C / KT) LOADK((kt + 1) * KT);
#pragma unroll
            for (int kk = 0; kk < KT; kk++) {
                float a[8];
                *reinterpret_cast<float4*>(&a[0]) =
                    *reinterpret_cast<float4*>(&dynf[boA + kk * 128 + ty * 8]);
                *reinterpret_cast<float4*>(&a[4]) =
                    *reinterpret_cast<float4*>(&dynf[boA + kk * 128 + ty * 8 + 4]);
                ulonglong2 bp0 = *reinterpret_cast<ulonglong2*>(&dynf[boB + kk * 96 + tx * 8]);
                ulonglong2 bp1 = *reinterpret_cast<ulonglong2*>(&dynf[boB + kk * 96 + tx * 8 + 4]);
#pragma unroll
                for (int r = 0; r < 8; r++) {
                    unsigned long long ad = dup2(a[r]);
                    acc2[r][0] = ffma2(ad, bp0.x, acc2[r][0]);
                    acc2[r][1] = ffma2(ad, bp0.y, acc2[r][1]);
                    acc2[r][2] = ffma2(ad, bp1.x, acc2[r][2]);
                    acc2[r][3] = ffma2(ad, bp1.y, acc2[r][3]);
                }
            }
            barg(1, 192);
        }
#undef LOADK
#undef LDB
#undef LDA

        float acc[8][8];
#pragma unroll
        for (int r = 0; r < 8; r++)
#pragma unroll
            for (int c = 0; c < 4; c++) {
                unsigned long long v = acc2[r][c];
                acc[r][2 * c]     = __uint_as_float((uint32_t)(v & 0xffffffffu));
                acc[r][2 * c + 1] = __uint_as_float((uint32_t)(v >> 32));
            }

        float sqi[8], sqj[8];
        const int jb = j0 + tx * 8;
        const bool jwr = (jb < N);
#pragma unroll
        for (int r = 0; r < 8; r++) {
            int gi = i0 + ty * 8 + r;
            sqi[r] = (gi < N) ? SQ[gi] : 0.f;
        }
#pragma unroll
        for (int c = 0; c < 8; c++) {
            int gj = jb + c;
            sqj[c] = (gj < N) ? SQ[gj] : 0.f;
        }
#pragma unroll
        for (int r = 0; r < 8; r++) {
#pragma unroll
            for (int c = 0; c < 8; c++)
                acc[r][c] = fmaxf(sqi[r] + sqj[c] - 2.f * acc[r][c], 0.f);
            int gi = i0 + ty * 8 + r;
            if (gi < N && jwr) {
#pragma unroll
                for (int c = 0; c < 8; c++) tmax = fmaxf(tmax, acc[r][c]);
                float* dst = &g_d2[(bN + gi) * N + jb];
                *reinterpret_cast<float4*>(dst)     = *reinterpret_cast<float4*>(&acc[r][0]);
                *reinterpret_cast<float4*>(dst + 4) = *reinterpret_cast<float4*>(&acc[r][4]);
            }
        }

        if (ti != tj) {
            float* Ts = dynf;    // 16 x 129, reuses A-buf region (fp32 group only)
            for (int s = 0; s < 6; s++) {
                barg(1, 192);
                if ((tx >> 1) == s) {
#pragma unroll
                    for (int c = 0; c < 8; c++)
#pragma unroll
                        for (int r = 0; r < 8; r++)
                            Ts[((tx & 1) * 8 + c) * 129 + ty * 8 + r] = acc[r][c];
                }
                barg(1, 192);
#pragma unroll
                for (int w2 = 0; w2 < 3; w2++) {
                    int slot = tid + 192 * w2;
                    if (slot < 512) {
                        int jr = slot >> 5, q4 = slot & 31;
                        int gj = j0 + s * 16 + jr, gi = i0 + q4 * 4;
                        if (gj < N && gi < N) {
                            float4 v = make_float4(Ts[jr * 129 + q4 * 4],
                                                   Ts[jr * 129 + q4 * 4 + 1],
                                                   Ts[jr * 129 + q4 * 4 + 2],
                                                   Ts[jr * 129 + q4 * 4 + 3]);
                            *reinterpret_cast<float4*>(&g_d2[(bN + gj) * N + gi]) = v;
                        }
                    }
                }
            }
        }
    } else {
        // ===================== TENSOR GROUP (2 warps, cols 96..127) ==========
        const int t2 = tid - 192;         // 0..63
        const int wr = t2 >> 5;           // 0..1 (row half)
        const int kq = lane & 3, rr = lane >> 2;
        float* TeS = dynf + 7168;         // 4608 floats, tensor-private

        const uint4* pah = reinterpret_cast<const uint4*>(
            g_ah + ((size_t)b * ASEGS + ti * 8 + wr * 4) * 4096) + lane;
        const uint4* pal = reinterpret_cast<const uint4*>(
            g_al + ((size_t)b * ASEGS + ti * 8 + wr * 4) * 4096) + lane;
        const uint2* pbh = reinterpret_cast<const uint2*>(
            g_bh + ((size_t)b * BSEGS + tj * 16 + 12) * 2048) + lane;
        const uint2* pbl = reinterpret_cast<const uint2*>(
            g_bl + ((size_t)b * BSEGS + tj * 16 + 12) * 2048) + lane;

        float D[4][4][4];
#pragma unroll
        for (int mf = 0; mf < 4; mf++)
#pragma unroll
            for (int nf = 0; nf < 4; nf++)
#pragma unroll
                for (int e = 0; e < 4; e++) D[mf][nf][e] = 0.f;

#pragma unroll 2
        for (int k8 = 0; k8 < 32; k8++) {
            uint4 AH[4], AL[4];
            uint2 BH[4], BL[4];
#pragma unroll
            for (int mf = 0; mf < 4; mf++) {
                AH[mf] = pah[mf * 1024];
                AL[mf] = pal[mf * 1024];
            }
#pragma unroll
            for (int nf = 0; nf < 4; nf++) {
                BH[nf] = pbh[nf * 1024];
                BL[nf] = pbl[nf * 1024];
            }
            pah += 32; pal += 32; pbh += 32; pbl += 32;
#pragma unroll
            for (int mf = 0; mf < 4; mf++) {
                uint32_t ah[4] = {AH[mf].x, AH[mf].y, AH[mf].z, AH[mf].w};
                uint32_t al[4] = {AL[mf].x, AL[mf].y, AL[mf].z, AL[mf].w};
#pragma unroll
                for (int nf = 0; nf < 4; nf++) {
                    uint32_t bh[2] = {BH[nf].x, BH[nf].y};
                    uint32_t bl[2] = {BL[nf].x, BL[nf].y};
                    mma8(D[mf][nf], ah, bl);
                    mma8(D[mf][nf], al, bh);
                    mma8(D[mf][nf], ah, bh);
                }
            }
        }

        // stage straight (pitch 36), write d2 rows i0.., cols j0+96..+127
#pragma unroll
        for (int mf = 0; mf < 4; mf++)
#pragma unroll
            for (int nf = 0; nf < 4; nf++) {
                int r0 = wr * 64 + mf * 16 + rr;
                int cl = nf * 8 + 2 * kq;
                TeS[r0 * 36 + cl]       = D[mf][nf][0];
                TeS[r0 * 36 + cl + 1]   = D[mf][nf][1];
                TeS[(r0 + 8) * 36 + cl]     = D[mf][nf][2];
                TeS[(r0 + 8) * 36 + cl + 1] = D[mf][nf][3];
            }
        barg(2, 64);
#pragma unroll
        for (int i = 0; i < 16; i++) {
            int slot = t2 + 64 * i;
            int row = slot >> 3, c4 = slot & 7;
            int gi = i0 + row, gj = j0 + 96 + c4 * 4;
            if (gi < N && gj < N) {
                float sqi = SQ[gi];
                float4 v = *reinterpret_cast<float4*>(&TeS[row * 36 + c4 * 4]);
                float4 o;
                o.x = fmaxf(sqi + SQ[gj + 0] - 2.f * v.x, 0.f);
                o.y = fmaxf(sqi + SQ[gj + 1] - 2.f * v.y, 0.f);
                o.z = fmaxf(sqi + SQ[gj + 2] - 2.f * v.z, 0.f);
                o.w = fmaxf(sqi + SQ[gj + 3] - 2.f * v.w, 0.f);
                tmax = fmaxf(tmax, fmaxf(fmaxf(o.x, o.y), fmaxf(o.z, o.w)));
                *reinterpret_cast<float4*>(&g_d2[(bN + gi) * N + gj]) = o;
            }
        }

        if (ti != tj) {
            barg(2, 64);
#pragma unroll
            for (int mf = 0; mf < 4; mf++)
#pragma unroll
                for (int nf = 0; nf < 4; nf++) {
                    int r0 = wr * 64 + mf * 16 + rr;
                    int cl = nf * 8 + 2 * kq;
                    TeS[cl * 132 + r0]           = D[mf][nf][0];
                    TeS[(cl + 1) * 132 + r0]     = D[mf][nf][1];
                    TeS[cl * 132 + r0 + 8]       = D[mf][nf][2];
                    TeS[(cl + 1) * 132 + r0 + 8] = D[mf][nf][3];
                }
            barg(2, 64);
#pragma unroll
            for (int i = 0; i < 16; i++) {
                int slot = t2 + 64 * i;
                int jr = slot >> 5, q4 = slot & 31;
                int gj = j0 + 96 + jr, gi = i0 + q4 * 4;
                if (gj < N && gi < N) {
                    float sqj = SQ[gj];
                    float4 v = *reinterpret_cast<float4*>(&TeS[jr * 132 + q4 * 4]);
                    float4 o;
                    o.x = fmaxf(SQ[gi + 0] + sqj - 2.f * v.x, 0.f);
                    o.y = fmaxf(SQ[gi + 1] + sqj - 2.f * v.y, 0.f);
                    o.z = fmaxf(SQ[gi + 2] + sqj - 2.f * v.z, 0.f);
                    o.w = fmaxf(SQ[gi + 3] + sqj - 2.f * v.w, 0.f);
                    *reinterpret_cast<float4*>(&g_d2[(bN + gj) * N + gi]) = o;
                }
            }
        }
    }

    __syncthreads();
    red[tid] = tmax;
    __syncthreads();
    for (int o = 128; o > 0; o >>= 1) {
        if (tid < o) red[tid] = fmaxf(red[tid], red[tid + o]);
        __syncthreads();
    }
    if (tid == 0) atomicMax(&g_maxb[b], __float_as_uint(red[0]));
}

// branchless sorted-5 insert
#define INS5(v) {                                   \
        float w_ = (v), t_;                         \
        t_ = fminf(b0, w_); w_ = fmaxf(b0, w_); b0 = t_; \
        t_ = fminf(b1, w_); w_ = fmaxf(b1, w_); b1 = t_; \
        t_ = fminf(b2, w_); w_ = fmaxf(b2, w_); b2 = t_; \
        t_ = fminf(b3, w_); w_ = fmaxf(b3, w_); b3 = t_; \
        b4 = fminf(b4, w_);                         \
    }

// 5-NN density — warp per row, PER-BATCH launch (reads d2 while L2-resident)
__global__ void knn_kernel(int b) {
    int w = (blockIdx.x * blockDim.x + threadIdx.x) >> 5;
    int lane = threadIdx.x & 31;
    if (w >= N) return;
    const int g = b * N + w;
    const float4* row = reinterpret_cast<const float4*>(&g_d2[(size_t)g * N]);
    float b0 = 3.4e38f, b1 = 3.4e38f, b2 = 3.4e38f, b3 = 3.4e38f, b4 = 3.4e38f;
#pragma unroll 4
    for (int q = lane; q < NQ; q += 32) {
        float4 v = row[q];
        float m4 = fminf(fminf(v.x, v.y), fminf(v.z, v.w));
        if (m4 < b4) {
            INS5(v.x); INS5(v.y); INS5(v.z); INS5(v.w);
        }
    }
    float s = 0.f;
#pragma unroll
    for (int t = 0; t < 5; t++) {
        float m = b0;
#pragma unroll
        for (int o = 16; o > 0; o >>= 1) m = fminf(m, __shfl_xor_sync(0xffffffffu, m, o));
        unsigned bal = __ballot_sync(0xffffffffu, b0 == m);
        if (lane == (__ffs(bal) - 1)) {
            b0 = b1; b1 = b2; b2 = b3; b3 = b4; b4 = 3.4e38f;
        }
        float d = sqrtf(m) / 16.0f;
        s = s + d * d;
    }
    if (lane == 0)
        g_dens[g] = expf(-(s / 5.0f)) + jax_uniform_noise(g) * 1e-6f;
}

// dist_parent + score — warp per row, PER-BATCH launch
__global__ void parent_kernel(int b) {
    int w = (blockIdx.x * blockDim.x + threadIdx.x) >> 5;
    int lane = threadIdx.x & 31;
    if (w >= N) return;
    const int g = b * N + w;
    float di = g_dens[g];
    const float4* row = reinterpret_cast<const float4*>(&g_d2[(size_t)g * N]);
    const float4* dr  = reinterpret_cast<const float4*>(&g_dens[(size_t)b * N]);
    float mn = 3.4e38f;
#pragma unroll 4
    for (int q = lane; q < NQ; q += 32) {
        float4 v = row[q];
        float m4 = fminf(fminf(v.x, v.y), fminf(v.z, v.w));
        if (m4 < mn) {
            float4 dd = dr[q];
            if (dd.x > di) mn = fminf(mn, v.x);
            if (dd.y > di) mn = fminf(mn, v.y);
            if (dd.z > di) mn = fminf(mn, v.z);
            if (dd.w > di) mn = fminf(mn, v.w);
        }
    }
#pragma unroll
    for (int o = 16; o > 0; o >>= 1) mn = fminf(mn, __shfl_xor_sync(0xffffffffu, mn, o));
    if (lane == 0) {
        float dmax = sqrtf(__uint_as_float(g_maxb[b])) / 16.0f;
        float dp = fminf(dmax, sqrtf(mn) / 16.0f);
        g_score[g] = dp * di;
    }
}

// per-batch top-50 with warp-shuffle reductions (lower index wins ties)
__global__ void topk_kernel() {
    int b = blockIdx.x;
    __shared__ float s[N];
    __shared__ float wv[32];
    __shared__ int   wix[32];
    int t = threadIdx.x, lane = t & 31, w = t >> 5;
    for (int i = t; i < N; i += 1024) s[i] = g_score[b * N + i];
    __syncthreads();
    for (int m = 0; m < NC; m++) {
        float bs = -3.4e38f;
        int   bi = N;
        for (int i = t; i < N; i += 1024) {
            float v = s[i];
            if (v > bs) { bs = v; bi = i; }
        }
#pragma unroll
        for (int o = 16; o > 0; o >>= 1) {
            float ov = __shfl_xor_sync(0xffffffffu, bs, o);
            int   oi = __shfl_xor_sync(0xffffffffu, bi, o);
            if (ov > bs || (ov == bs && oi < bi)) { bs = ov; bi = oi; }
        }
        if (lane == 0) { wv[w] = bs; wix[w] = bi; }
        __syncthreads();
        if (w == 0) {
            bs = wv[lane]; bi = wix[lane];
#pragma unroll
            for (int o = 16; o > 0; o >>= 1) {
                float ov = __shfl_xor_sync(0xffffffffu, bs, o);
                int   oi = __shfl_xor_sync(0xffffffffu, bi, o);
                if (ov > bs || (ov == bs && oi < bi)) { bs = ov; bi = oi; }
            }
            if (lane == 0) { g_idx[b * NC + m] = bi; s[bi] = -3.4e38f; }
        }
        __syncthreads();
    }
}

__global__ void gather_kernel(const float* __restrict__ x, float* __restrict__ out) {
    int g = blockIdx.x * blockDim.x + threadIdx.x;
    if (g >= B * C * NC) return;
    int m = g % NC;
    int c = (g / NC) % C;
    int b = g / (NC * C);
    int idx = g_idx[b * NC + m];
    out[g] = x[(size_t)b * C * N + (size_t)c * N + idx];
}

// ---------------- launch -----------------------------------------------------
extern "C" void kernel_launch(void* const* d_in, const int* in_sizes, int n_in,
                              void* d_out, int out_size) {
    const float* x = (const float*)d_in[0];
    float* out = (float*)d_out;

    cudaFuncSetAttribute(gram_kernel,
                         cudaFuncAttributeMaxDynamicSharedMemorySize, DSMEM_BYTES);

    init_kernel<<<1, 32>>>();
    sq_kernel<<<(B * N + 255) / 256, 256>>>(x);
    dim3 sg(ASEGS, B);
    split_kernel<<<sg, 256>>>(x);

    // per-batch interleaving: knn/parent read d2 while it is still L2-resident
    const int rows_grid = (N * 32 + 255) / 256;
    for (int b = 0; b < B; b++) {
        gram_kernel<<<NPAIRS, 256, DSMEM_BYTES>>>(x, b);
        knn_kernel<<<rows_grid, 256>>>(b);
        parent_kernel<<<rows_grid, 256>>>(b);
    }
    topk_kernel<<<B, 1024>>>();
    gather_kernel<<<(B * C * NC + 255) / 256, 256>>>(x, out);
}

// round 15
// speedup vs baseline: 1.3979x; 1.3979x over previous
#include <cuda_runtime.h>
#include <cstdint>

#define B 8
#define C 256
#define N 3136
#define NP 3200
#define NQ (N/4)
#define NC 50
#define TILE 128
#define KT 16
#define NT 25
#define NPAIRS (NT*(NT+1)/2)
#define ASEGS 200              // NP/16
#define BSEGS 400              // NP/8
#define DSMEM_BYTES 47104      // 11776 floats

// ---------------- scratch (static device globals: allocation-guard safe) ----
__device__ float g_d2[(size_t)B * N * N];
__device__ __align__(16) float g_ah[(size_t)B * ASEGS * 32 * 128];
__device__ __align__(16) float g_al[(size_t)B * ASEGS * 32 * 128];
__device__ __align__(16) float g_bh[(size_t)B * BSEGS * 32 * 64];
__device__ __align__(16) float g_bl[(size_t)B * BSEGS * 32 * 64];
__device__ float    g_sq[B * N];
__device__ float    g_dens[B * N];
__device__ float    g_score[B * N];
__device__ unsigned g_maxb[B];
__device__ int      g_idx[B * NC];

// ---------------- threefry-2x32 (JAX-compatible) ---------------------------
__device__ __forceinline__ uint32_t rotl32(uint32_t x, int r) {
    return (x << r) | (x >> (32 - r));
}

__device__ __forceinline__ void threefry2x32_k42(uint32_t x0, uint32_t x1,
                                                 uint32_t& o0, uint32_t& o1) {
    const uint32_t ks0 = 0u;
    const uint32_t ks1 = 42u;
    const uint32_t ks2 = 0x1BD11BDAu ^ 42u;
    x0 += ks0; x1 += ks1;
#define TF_RND(r) { x0 += x1; x1 = rotl32(x1, r); x1 ^= x0; }
    TF_RND(13) TF_RND(15) TF_RND(26) TF_RND(6)
    x0 += ks1; x1 += ks2 + 1u;
    TF_RND(17) TF_RND(29) TF_RND(16) TF_RND(24)
    x0 += ks2; x1 += ks0 + 2u;
    TF_RND(13) TF_RND(15) TF_RND(26) TF_RND(6)
    x0 += ks0; x1 += ks1 + 3u;
    TF_RND(17) TF_RND(29) TF_RND(16) TF_RND(24)
    x0 += ks1; x1 += ks2 + 4u;
    TF_RND(13) TF_RND(15) TF_RND(26) TF_RND(6)
    x0 += ks2; x1 += ks0 + 5u;
#undef TF_RND
    o0 = x0; o1 = x1;
}

__device__ __forceinline__ float jax_uniform_noise(int g) {
    const int half = (B * N) / 2;  // 12544
    uint32_t lane = (g < half) ? (uint32_t)g : (uint32_t)(g - half);
    uint32_t o0, o1;
    threefry2x32_k42(lane, lane + (uint32_t)half, o0, o1);
    uint32_t bits = (g < half) ? o0 : o1;
    return __uint_as_float((bits >> 9) | 0x3F800000u) - 1.0f;
}

// ---------------- tf32 + f32x2 helpers ---------------------------------------
__device__ __forceinline__ uint32_t tf32r(float x) {
    uint32_t y;
    asm("cvt.rna.tf32.f32 %0, %1;" : "=r"(y) : "f"(x));
    return y;
}

__device__ __forceinline__ void split1(float v, float& h, float& l) {
    float hf = __uint_as_float(tf32r(v));
    h = hf;
    l = __uint_as_float(tf32r(v - hf));
}

__device__ __forceinline__ void mma8(float d[4], const uint32_t a[4], const uint32_t b[2]) {
    asm volatile(
        "mma.sync.aligned.m16n8k8.row.col.f32.tf32.tf32.f32 "
        "{%0,%1,%2,%3}, {%4,%5,%6,%7}, {%8,%9}, {%0,%1,%2,%3};"
        : "+f"(d[0]), "+f"(d[1]), "+f"(d[2]), "+f"(d[3])
        : "r"(a[0]), "r"(a[1]), "r"(a[2]), "r"(a[3]), "r"(b[0]), "r"(b[1]));
}

__device__ __forceinline__ unsigned long long ffma2(unsigned long long a,
                                                    unsigned long long b,
                                                    unsigned long long c) {
    unsigned long long d;
    asm("fma.rn.f32x2 %0, %1, %2, %3;" : "=l"(d) : "l"(a), "l"(b), "l"(c));
    return d;
}

__device__ __forceinline__ unsigned long long dup2(float a) {
    unsigned long long d;
    asm("mov.b64 %0, {%1, %1};" : "=l"(d) : "f"(a));
    return d;
}

__device__ __forceinline__ void barg(int id, int cnt) {
    asm volatile("bar.sync %0, %1;" :: "r"(id), "r"(cnt) : "memory");
}

// L2-only (L1-bypass) vector loads for the tensor fragment stream
__device__ __forceinline__ uint4 ldcg4(const uint4* p) {
    uint4 v;
    asm volatile("ld.global.cg.v4.u32 {%0,%1,%2,%3}, [%4];"
                 : "=r"(v.x), "=r"(v.y), "=r"(v.z), "=r"(v.w) : "l"(p));
    return v;
}

__device__ __forceinline__ uint2 ldcg2(const uint2* p) {
    uint2 v;
    asm volatile("ld.global.cg.v2.u32 {%0,%1}, [%2];"
                 : "=r"(v.x), "=r"(v.y) : "l"(p));
    return v;
}

// ---------------- kernels ---------------------------------------------------
__global__ void init_kernel() {
    int t = threadIdx.x;
    if (t < B) g_maxb[t] = 0u;
}

__global__ void sq_kernel(const float* __restrict__ x) {
    int g = blockIdx.x * blockDim.x + threadIdx.x;
    if (g >= B * N) return;
    int b = g / N, n = g % N;
    const float* p = x + (size_t)b * C * N + n;
    float s = 0.f;
#pragma unroll 8
    for (int c = 0; c < C; c++) {
        float v = p[(size_t)c * N];
        s = fmaf(v, v, s);
    }
    g_sq[g] = s;
}

// transpose + tf32 hi/lo split into global fragment layouts (tensor operands)
__global__ void split_kernel(const float* __restrict__ x) {
    const int seg = blockIdx.x;
    const int b = blockIdx.y;
    const int row0 = seg * 16;
    __shared__ float sv[16][260];
    const int t = threadIdx.x;
#pragma unroll
    for (int i = 0; i < 16; i++) {
        int r = t & 15;
        int k = (t >> 4) + i * 16;
        int row = row0 + r;
        float v = (row < N) ? x[((size_t)b * C + k) * N + row] : 0.f;
        sv[r][k] = v;
    }
    __syncthreads();
#pragma unroll
    for (int j = 0; j < 4; j++) {
        int u = t + j * 256;
        int k8 = u >> 5, lane = u & 31;
        int rl = lane >> 2, tg = lane & 3;
        int k = k8 * 8 + tg;
        float4 hv, lv;
        split1(sv[rl][k],         hv.x, lv.x);
        split1(sv[rl + 8][k],     hv.y, lv.y);
        split1(sv[rl][k + 4],     hv.z, lv.z);
        split1(sv[rl + 8][k + 4], hv.w, lv.w);
        size_t base = (((size_t)b * ASEGS + seg) * 32 + k8) * 128 + lane * 4;
        *reinterpret_cast<float4*>(&g_ah[base]) = hv;
        *reinterpret_cast<float4*>(&g_al[base]) = lv;
    }
#pragma unroll
    for (int j = 0; j < 8; j++) {
        int u = t + j * 256;
        int cs = u >> 10, rem = u & 1023;
        int k8 = rem >> 5, lane = rem & 31;
        int col = cs * 8 + (lane >> 2), tg = lane & 3;
        int k = k8 * 8 + tg;
        float2 hv, lv;
        split1(sv[col][k],     hv.x, lv.x);
        split1(sv[col][k + 4], hv.y, lv.y);
        size_t base = (((size_t)b * BSEGS + seg * 2 + cs) * 32 + k8) * 64 + lane * 2;
        *reinterpret_cast<float2*>(&g_bh[base]) = hv;
        *reinterpret_cast<float2*>(&g_bl[base]) = lv;
    }
}

// INTRA-CTA HYBRID Gram (R11 config, monolithic): warps 0-5 = fp32 f32x2
// (cols 0..95), warps 6-7 = tf32x3 mma.sync (cols 96..127) with L1-bypass
// fragment loads (ld.global.cg) to free the L1 port for the fp32 group's LDS.
__global__ __launch_bounds__(256, 2) void gram_kernel(const float* __restrict__ x) {
    extern __shared__ float dynf[];
    __shared__ float red[256];

    const int b = blockIdx.z;
    int rem = blockIdx.x;
    int ti = 0;
    while (rem >= NT - ti) { rem -= NT - ti; ti++; }
    const int tj = ti + rem;
    const int i0 = ti * TILE, j0 = tj * TILE;

    const int tid = threadIdx.x, lane = tid & 31;
    const float* SQ = &g_sq[b * N];
    const size_t bN = (size_t)b * N;
    float tmax = 0.f;
    const float4 f40 = make_float4(0.f, 0.f, 0.f, 0.f);

    if (tid < 192) {
        // ===================== FP32 GROUP (6 warps, cols 0..95) ==============
        const float* X = x + (size_t)b * C * N;
        const int tx = tid % 12, ty = tid / 12;

        float4 pa0, pa1, pa2, pb0, pb1;
#define LDA(s, dst, k0) { int kk_=(s)>>5, f4_=(s)&31; int ic_=i0+f4_*4;       \
        dst = (ic_<N)? *reinterpret_cast<const float4*>(&X[(size_t)((k0)+kk_)*N+ic_]) : f40; }
#define LDB(s, dst, k0) { int kk_=(s)/24, c_=(s)%24; int jc_=j0+c_*4;         \
        dst = (jc_<N)? *reinterpret_cast<const float4*>(&X[(size_t)((k0)+kk_)*N+jc_]) : f40; }
#define LOADK(k0) { LDA(tid, pa0, k0); LDA(tid+192, pa1, k0);                  \
        if (tid < 128) LDA(tid+384, pa2, k0);                                  \
        LDB(tid, pb0, k0); LDB(tid+192, pb1, k0); }

        unsigned long long acc2[8][4];
#pragma unroll
        for (int r = 0; r < 8; r++)
#pragma unroll
            for (int c = 0; c < 4; c++) acc2[r][c] = 0ull;

        LOADK(0);
#pragma unroll 2
        for (int kt = 0; kt < C / KT; kt++) {
            const int boA = (kt & 1) * 2048;
            const int boB = 4096 + (kt & 1) * 1536;
            { int s=tid;     *reinterpret_cast<float4*>(&dynf[boA+(s>>5)*128+(s&31)*4]) = pa0; }
            { int s=tid+192; *reinterpret_cast<float4*>(&dynf[boA+(s>>5)*128+(s&31)*4]) = pa1; }
            if (tid < 128) { int s=tid+384; *reinterpret_cast<float4*>(&dynf[boA+(s>>5)*128+(s&31)*4]) = pa2; }
            { int s=tid;     *reinterpret_cast<float4*>(&dynf[boB+(s/24)*96+(s%24)*4]) = pb0; }
            { int s=tid+192; *reinterpret_cast<float4*>(&dynf[boB+(s/24)*96+(s%24)*4]) = pb1; }
            barg(1, 192);
            if (kt + 1 < C / KT) LOADK((kt + 1) * KT);
#pragma unroll
            for (int kk = 0; kk < KT; kk++) {
                float a[8];
                *reinterpret_cast<float4*>(&a[0]) =
                    *reinterpret_cast<float4*>(&dynf[boA + kk * 128 + ty * 8]);
                *reinterpret_cast<float4*>(&a[4]) =
                    *reinterpret_cast<float4*>(&dynf[boA + kk * 128 + ty * 8 + 4]);
                ulonglong2 bp0 = *reinterpret_cast<ulonglong2*>(&dynf[boB + kk * 96 + tx * 8]);
                ulonglong2 bp1 = *reinterpret_cast<ulonglong2*>(&dynf[boB + kk * 96 + tx * 8 + 4]);
#pragma unroll
                for (int r = 0; r < 8; r++) {
                    unsigned long long ad = dup2(a[r]);
                    acc2[r][0] = ffma2(ad, bp0.x, acc2[r][0]);
                    acc2[r][1] = ffma2(ad, bp0.y, acc2[r][1]);
                    acc2[r][2] = ffma2(ad, bp1.x, acc2[r][2]);
                    acc2[r][3] = ffma2(ad, bp1.y, acc2[r][3]);
                }
            }
            barg(1, 192);
        }
#undef LOADK
#undef LDB
#undef LDA

        float acc[8][8];
#pragma unroll
        for (int r = 0; r < 8; r++)
#pragma unroll
            for (int c = 0; c < 4; c++) {
                unsigned long long v = acc2[r][c];
                acc[r][2 * c]     = __uint_as_float((uint32_t)(v & 0xffffffffu));
                acc[r][2 * c + 1] = __uint_as_float((uint32_t)(v >> 32));
            }

        float sqi[8], sqj[8];
        const int jb = j0 + tx * 8;
        const bool jwr = (jb < N);
#pragma unroll
        for (int r = 0; r < 8; r++) {
            int gi = i0 + ty * 8 + r;
            sqi[r] = (gi < N) ? SQ[gi] : 0.f;
        }
#pragma unroll
        for (int c = 0; c < 8; c++) {
            int gj = jb + c;
            sqj[c] = (gj < N) ? SQ[gj] : 0.f;
        }
#pragma unroll
        for (int r = 0; r < 8; r++) {
#pragma unroll
            for (int c = 0; c < 8; c++)
                acc[r][c] = fmaxf(sqi[r] + sqj[c] - 2.f * acc[r][c], 0.f);
            int gi = i0 + ty * 8 + r;
            if (gi < N && jwr) {
#pragma unroll
                for (int c = 0; c < 8; c++) tmax = fmaxf(tmax, acc[r][c]);
                float* dst = &g_d2[(bN + gi) * N + jb];
                *reinterpret_cast<float4*>(dst)     = *reinterpret_cast<float4*>(&acc[r][0]);
                *reinterpret_cast<float4*>(dst + 4) = *reinterpret_cast<float4*>(&acc[r][4]);
            }
        }

        if (ti != tj) {
            float* Ts = dynf;    // 16 x 129, reuses A-buf region (fp32 group only)
            for (int s = 0; s < 6; s++) {
                barg(1, 192);
                if ((tx >> 1) == s) {
#pragma unroll
                    for (int c = 0; c < 8; c++)
#pragma unroll
                        for (int r = 0; r < 8; r++)
                            Ts[((tx & 1) * 8 + c) * 129 + ty * 8 + r] = acc[r][c];
                }
                barg(1, 192);
#pragma unroll
                for (int w2 = 0; w2 < 3; w2++) {
                    int slot = tid + 192 * w2;
                    if (slot < 512) {
                        int jr = slot >> 5, q4 = slot & 31;
                        int gj = j0 + s * 16 + jr, gi = i0 + q4 * 4;
                        if (gj < N && gi < N) {
                            float4 v = make_float4(Ts[jr * 129 + q4 * 4],
                                                   Ts[jr * 129 + q4 * 4 + 1],
                                                   Ts[jr * 129 + q4 * 4 + 2],
                                                   Ts[jr * 129 + q4 * 4 + 3]);
                            *reinterpret_cast<float4*>(&g_d2[(bN + gj) * N + gi]) = v;
                        }
                    }
                }
            }
        }
    } else {
        // ===================== TENSOR GROUP (2 warps, cols 96..127) ==========
        const int t2 = tid - 192;         // 0..63
        const int wr = t2 >> 5;           // 0..1 (row half)
        const int kq = lane & 3, rr = lane >> 2;
        float* TeS = dynf + 7168;         // 4608 floats, tensor-private

        const uint4* pah = reinterpret_cast<const uint4*>(
            g_ah + ((size_t)b * ASEGS + ti * 8 + wr * 4) * 4096) + lane;
        const uint4* pal = reinterpret_cast<const uint4*>(
            g_al + ((size_t)b * ASEGS + ti * 8 + wr * 4) * 4096) + lane;
        const uint2* pbh = reinterpret_cast<const uint2*>(
            g_bh + ((size_t)b * BSEGS + tj * 16 + 12) * 2048) + lane;
        const uint2* pbl = reinterpret_cast<const uint2*>(
            g_bl + ((size_t)b * BSEGS + tj * 16 + 12) * 2048) + lane;

        float D[4][4][4];
#pragma unroll
        for (int mf = 0; mf < 4; mf++)
#pragma unroll
            for (int nf = 0; nf < 4; nf++)
#pragma unroll
                for (int e = 0; e < 4; e++) D[mf][nf][e] = 0.f;

#pragma unroll 2
        for (int k8 = 0; k8 < 32; k8++) {
            uint4 AH[4], AL[4];
            uint2 BH[4], BL[4];
#pragma unroll
            for (int mf = 0; mf < 4; mf++) {
                AH[mf] = ldcg4(pah + mf * 1024);
                AL[mf] = ldcg4(pal + mf * 1024);
            }
#pragma unroll
            for (int nf = 0; nf < 4; nf++) {
                BH[nf] = ldcg2(pbh + nf * 1024);
                BL[nf] = ldcg2(pbl + nf * 1024);
            }
            pah += 32; pal += 32; pbh += 32; pbl += 32;
#pragma unroll
            for (int mf = 0; mf < 4; mf++) {
                uint32_t ah[4] = {AH[mf].x, AH[mf].y, AH[mf].z, AH[mf].w};
                uint32_t al[4] = {AL[mf].x, AL[mf].y, AL[mf].z, AL[mf].w};
#pragma unroll
                for (int nf = 0; nf < 4; nf++) {
                    uint32_t bh[2] = {BH[nf].x, BH[nf].y};
                    uint32_t bl[2] = {BL[nf].x, BL[nf].y};
                    mma8(D[mf][nf], ah, bl);
                    mma8(D[mf][nf], al, bh);
                    mma8(D[mf][nf], ah, bh);
                }
            }
        }

        // stage straight (pitch 36), write d2 rows i0.., cols j0+96..+127
#pragma unroll
        for (int mf = 0; mf < 4; mf++)
#pragma unroll
            for (int nf = 0; nf < 4; nf++) {
                int r0 = wr * 64 + mf * 16 + rr;
                int cl = nf * 8 + 2 * kq;
                TeS[r0 * 36 + cl]       = D[mf][nf][0];
                TeS[r0 * 36 + cl + 1]   = D[mf][nf][1];
                TeS[(r0 + 8) * 36 + cl]     = D[mf][nf][2];
                TeS[(r0 + 8) * 36 + cl + 1] = D[mf][nf][3];
            }
        barg(2, 64);
#pragma unroll
        for (int i = 0; i < 16; i++) {
            int slot = t2 + 64 * i;
            int row = slot >> 3, c4 = slot & 7;
            int gi = i0 + row, gj = j0 + 96 + c4 * 4;
            if (gi < N && gj < N) {
                float sqi = SQ[gi];
                float4 v = *reinterpret_cast<float4*>(&TeS[row * 36 + c4 * 4]);
                float4 o;
                o.x = fmaxf(sqi + SQ[gj + 0] - 2.f * v.x, 0.f);
                o.y = fmaxf(sqi + SQ[gj + 1] - 2.f * v.y, 0.f);
                o.z = fmaxf(sqi + SQ[gj + 2] - 2.f * v.z, 0.f);
                o.w = fmaxf(sqi + SQ[gj + 3] - 2.f * v.w, 0.f);
                tmax = fmaxf(tmax, fmaxf(fmaxf(o.x, o.y), fmaxf(o.z, o.w)));
                *reinterpret_cast<float4*>(&g_d2[(bN + gi) * N + gj]) = o;
            }
        }

        if (ti != tj) {
            barg(2, 64);
#pragma unroll
            for (int mf = 0; mf < 4; mf++)
#pragma unroll
                for (int nf = 0; nf < 4; nf++) {
                    int r0 = wr * 64 + mf * 16 + rr;
                    int cl = nf * 8 + 2 * kq;
                    TeS[cl * 132 + r0]           = D[mf][nf][0];
                    TeS[(cl + 1) * 132 + r0]     = D[mf][nf][1];
                    TeS[cl * 132 + r0 + 8]       = D[mf][nf][2];
                    TeS[(cl + 1) * 132 + r0 + 8] = D[mf][nf][3];
                }
            barg(2, 64);
#pragma unroll
            for (int i = 0; i < 16; i++) {
                int slot = t2 + 64 * i;
                int jr = slot >> 5, q4 = slot & 31;
                int gj = j0 + 96 + jr, gi = i0 + q4 * 4;
                if (gj < N && gi < N) {
                    float sqj = SQ[gj];
                    float4 v = *reinterpret_cast<float4*>(&TeS[jr * 132 + q4 * 4]);
                    float4 o;
                    o.x = fmaxf(SQ[gi + 0] + sqj - 2.f * v.x, 0.f);
                    o.y = fmaxf(SQ[gi + 1] + sqj - 2.f * v.y, 0.f);
                    o.z = fmaxf(SQ[gi + 2] + sqj - 2.f * v.z, 0.f);
                    o.w = fmaxf(SQ[gi + 3] + sqj - 2.f * v.w, 0.f);
                    *reinterpret_cast<float4*>(&g_d2[(bN + gj) * N + gi]) = o;
                }
            }
        }
    }

    __syncthreads();
    red[tid] = tmax;
    __syncthreads();
    for (int o = 128; o > 0; o >>= 1) {
        if (tid < o) red[tid] = fmaxf(red[tid], red[tid + o]);
        __syncthreads();
    }
    if (tid == 0) atomicMax(&g_maxb[b], __float_as_uint(red[0]));
}

// branchless sorted-5 insert
#define INS5(v) {                                   \
        float w_ = (v), t_;                         \
        t_ = fminf(b0, w_); w_ = fmaxf(b0, w_); b0 = t_; \
        t_ = fminf(b1, w_); w_ = fmaxf(b1, w_); b1 = t_; \
        t_ = fminf(b2, w_); w_ = fmaxf(b2, w_); b2 = t_; \
        t_ = fminf(b3, w_); w_ = fmaxf(b3, w_); b3 = t_; \
        b4 = fminf(b4, w_);                         \
    }

// 5-NN density — warp per row, guarded fast-path (skips are exact no-ops)
__global__ void knn_kernel() {
    int w = (blockIdx.x * blockDim.x + threadIdx.x) >> 5;
    int lane = threadIdx.x & 31;
    if (w >= B * N) return;
    const float4* row = reinterpret_cast<const float4*>(&g_d2[(size_t)w * N]);
    float b0 = 3.4e38f, b1 = 3.4e38f, b2 = 3.4e38f, b3 = 3.4e38f, b4 = 3.4e38f;
#pragma unroll 4
    for (int q = lane; q < NQ; q += 32) {
        float4 v = row[q];
        float m4 = fminf(fminf(v.x, v.y), fminf(v.z, v.w));
        if (m4 < b4) {
            INS5(v.x); INS5(v.y); INS5(v.z); INS5(v.w);
        }
    }
    float s = 0.f;
#pragma unroll
    for (int t = 0; t < 5; t++) {
        float m = b0;
#pragma unroll
        for (int o = 16; o > 0; o >>= 1) m = fminf(m, __shfl_xor_sync(0xffffffffu, m, o));
        unsigned bal = __ballot_sync(0xffffffffu, b0 == m);
        if (lane == (__ffs(bal) - 1)) {
            b0 = b1; b1 = b2; b2 = b3; b3 = b4; b4 = 3.4e38f;
        }
        float d = sqrtf(m) / 16.0f;
        s = s + d * d;
    }
    if (lane == 0)
        g_dens[w] = expf(-(s / 5.0f)) + jax_uniform_noise(w) * 1e-6f;
}

// dist_parent + score — warp per row, guarded fast-path
__global__ void parent_kernel() {
    int w = (blockIdx.x * blockDim.x + threadIdx.x) >> 5;
    int lane = threadIdx.x & 31;
    if (w >= B * N) return;
    int b = w / N;
    float di = g_dens[w];
    const float4* row = reinterpret_cast<const float4*>(&g_d2[(size_t)w * N]);
    const float4* dr  = reinterpret_cast<const float4*>(&g_dens[(size_t)b * N]);
    float mn = 3.4e38f;
#pragma unroll 4
    for (int q = lane; q < NQ; q += 32) {
        float4 v = row[q];
        float m4 = fminf(fminf(v.x, v.y), fminf(v.z, v.w));
        if (m4 < mn) {
            float4 dd = dr[q];
            if (dd.x > di) mn = fminf(mn, v.x);
            if (dd.y > di) mn = fminf(mn, v.y);
            if (dd.z > di) mn = fminf(mn, v.z);
            if (dd.w > di) mn = fminf(mn, v.w);
        }
    }
#pragma unroll
    for (int o = 16; o > 0; o >>= 1) mn = fminf(mn, __shfl_xor_sync(0xffffffffu, mn, o));
    if (lane == 0) {
        float dmax = sqrtf(__uint_as_float(g_maxb[b])) / 16.0f;
        float dp = fminf(dmax, sqrtf(mn) / 16.0f);
        g_score[w] = dp * di;
    }
}

// per-batch top-50 with warp-shuffle reductions (lower index wins ties)
__global__ void topk_kernel() {
    int b = blockIdx.x;
    __shared__ float s[N];
    __shared__ float wv[32];
    __shared__ int   wix[32];
    int t = threadIdx.x, lane = t & 31, w = t >> 5;
    for (int i = t; i < N; i += 1024) s[i] = g_score[b * N + i];
    __syncthreads();
    for (int m = 0; m < NC; m++) {
        float bs = -3.4e38f;
        int   bi = N;
        for (int i = t; i < N; i += 1024) {
            float v = s[i];
            if (v > bs) { bs = v; bi = i; }
        }
#pragma unroll
        for (int o = 16; o > 0; o >>= 1) {
            float ov = __shfl_xor_sync(0xffffffffu, bs, o);
            int   oi = __shfl_xor_sync(0xffffffffu, bi, o);
            if (ov > bs || (ov == bs && oi < bi)) { bs = ov; bi = oi; }
        }
        if (lane == 0) { wv[w] = bs; wix[w] = bi; }
        __syncthreads();
        if (w == 0) {
            bs = wv[lane]; bi = wix[lane];
#pragma unroll
            for (int o = 16; o > 0; o >>= 1) {
                float ov = __shfl_xor_sync(0xffffffffu, bs, o);
                int   oi = __shfl_xor_sync(0xffffffffu, bi, o);
                if (ov > bs || (ov == bs && oi < bi)) { bs = ov; bi = oi; }
            }
            if (lane == 0) { g_idx[b * NC + m] = bi; s[bi] = -3.4e38f; }
        }
        __syncthreads();
    }
}

__global__ void gather_kernel(const float* __restrict__ x, float* __restrict__ out) {
    int g = blockIdx.x * blockDim.x + threadIdx.x;
    if (g >= B * C * NC) return;
    int m = g % NC;
    int c = (g / NC) % C;
    int b = g / (NC * C);
    int idx = g_idx[b * NC + m];
    out[g] = x[(size_t)b * C * N + (size_t)c * N + idx];
}

// ---------------- launch -----------------------------------------------------
extern "C" void kernel_launch(void* const* d_in, const int* in_sizes, int n_in,
                              void* d_out, int out_size) {
    const float* x = (const float*)d_in[0];
    float* out = (float*)d_out;

    cudaFuncSetAttribute(gram_kernel,
                         cudaFuncAttributeMaxDynamicSharedMemorySize, DSMEM_BYTES);

    init_kernel<<<1, 32>>>();
    sq_kernel<<<(B * N + 255) / 256, 256>>>(x);
    dim3 sg(ASEGS, B);
    split_kernel<<<sg, 256>>>(x);
    dim3 gg(NPAIRS, 1, B);
    gram_kernel<<<gg, 256, DSMEM_BYTES>>>(x);
    int rows = B * N;
    knn_kernel<<<(rows * 32 + 255) / 256, 256>>>();
    parent_kernel<<<(rows * 32 + 255) / 256, 256>>>();
    topk_kernel<<<B, 1024>>>();
    gather_kernel<<<(B * C * NC + 255) / 256, 256>>>(x, out);
}